// round 15
// baseline (speedup 1.0000x reference)
#include <cuda_runtime.h>
#include <cuda_bf16.h>

// emdModule: exact NN via uniform-grid spatial hashing + 50-step recurrence.
// BOTH point sets are cell-sorted: candidate loads of neighboring queries hit
// the same cache lines (queries in a warp are spatially adjacent). 8 lanes per
// query fast path (r=1 cube); warp-cooperative slow path for r>=2.
//
// EXACTNESS (outputs bit-identical to the passing brute-force kernels):
//  - d2 per examined candidate uses the identical rounded op sequence:
//      w     = (a*a + b*b) + c*c          (mul/add, no fma)
//      inner = fma(z,c, fma(y,b, x*a))
//      d2    = fma(-2, inner, sq1 + w)
//  - selection = min over packed key (bits(d2)<<32 | j): order- and
//    duplication-independent; ties -> smaller j == jnp.argmin first-index.
//  - completeness: after the Chebyshev<=r cube, any unexamined point is >= r
//    cells away on some axis => exact dist >= r*h => rounded d2 >= (r*h)^2-2e-6.
//    Stop only when best_d2 < (r*h)^2 - 1e-5; r == G covers the whole grid.
//  - query processing order is irrelevant (per-row independent); results are
//    scattered to the original row.
//  - epilogue identical: cmin = sqrt(max(d2,0)); iters x {m = cmin - price;
//    price += eps*m}; outputs sqrt(m), assignment.

#define BATCH 16
#define NPTS 2048
#define ROWS (BATCH * NPTS)   // 32768
#define G 16                  // grid resolution per axis
#define CELLS (G * G * G)     // 4096
#define HCELL 0.0625f         // 1/G, exactly representable

__device__ float4 g_pts[BATCH * NPTS];          // x2 {a,b,c, j-bits} sorted
__device__ int    g_cs[BATCH * (CELLS + 1)];    // x2 cell starts + sentinel
__device__ float4 g_qpts[BATCH * NPTS];         // x1 {x,y,z, i-bits} sorted
__device__ int    g_qcs[BATCH * (CELLS + 1)];   // x1 cell starts (unused)

__device__ __forceinline__ int cell_coord(float v) {
    int c = (int)(v * (float)G);
    return c < 0 ? 0 : (c > G - 1 ? G - 1 : c);
}

// -------- Kernel A: counting sort into cells (runs for x2 AND x1) ----------
#define TPB_A 512
#define PPT_A (NPTS / TPB_A)      // 4 points per thread
#define CPT_A (CELLS / TPB_A)     // 8 cells per thread

__global__ void __launch_bounds__(TPB_A) emd_bin_kernel(
    const float* __restrict__ x2, const float* __restrict__ x1) {
    int which = blockIdx.x >> 4;                  // 0: candidates, 1: queries
    int b     = blockIdx.x & (BATCH - 1);
    const float* src = which ? x1 : x2;
    float4* opts = (which ? g_qpts : g_pts) + b * NPTS;
    int*    ocs  = (which ? g_qcs  : g_cs)  + b * (CELLS + 1);
    int t = threadIdx.x;
    __shared__ int cnt[CELLS];
    __shared__ int wsum[16];

    for (int c = t; c < CELLS; c += TPB_A) cnt[c] = 0;
    __syncthreads();

    int   cellof[PPT_A];
    float px[PPT_A], py[PPT_A], pz[PPT_A];
    #pragma unroll
    for (int s = 0; s < PPT_A; s++) {
        int k = t + s * TPB_A;
        const float* p = src + ((long)b * NPTS + k) * 3;
        float a = p[0], bb = p[1], cc = p[2];
        int c = (cell_coord(cc) * G + cell_coord(bb)) * G + cell_coord(a);
        px[s] = a; py[s] = bb; pz[s] = cc; cellof[s] = c;
        atomicAdd(&cnt[c], 1);
    }
    __syncthreads();

    int loc[CPT_A], tsum = 0;
    #pragma unroll
    for (int u = 0; u < CPT_A; u++) { loc[u] = cnt[t * CPT_A + u]; tsum += loc[u]; }
    int lane = t & 31, wid = t >> 5;
    int incl = tsum;
    #pragma unroll
    for (int off = 1; off < 32; off <<= 1) {
        int v = __shfl_up_sync(0xFFFFFFFFu, incl, off);
        if (lane >= off) incl += v;
    }
    if (lane == 31) wsum[wid] = incl;
    __syncthreads();
    if (t == 0) {
        int acc = 0;
        #pragma unroll
        for (int w = 0; w < 16; w++) { int v = wsum[w]; wsum[w] = acc; acc += v; }
    }
    __syncthreads();
    int run = wsum[wid] + (incl - tsum);
    __syncthreads();
    #pragma unroll
    for (int u = 0; u < CPT_A; u++) {
        int c = t * CPT_A + u;
        ocs[c] = run;
        cnt[c] = run;
        run += loc[u];
    }
    if (t == 0) ocs[CELLS] = NPTS;
    __syncthreads();

    #pragma unroll
    for (int s = 0; s < PPT_A; s++) {
        int k = t + s * TPB_A;
        int slot = atomicAdd(&cnt[cellof[s]], 1);
        opts[slot] = make_float4(px[s], py[s], pz[s], __int_as_float(k));
    }
}

// ---------------- Kernel B: grid NN query + epilogue -----------------------
typedef unsigned long long u64;
#define TPB_B 256
#define GSIZE 8
#define QPB (TPB_B / GSIZE)       // 32 queries per block (one batch per block)

__global__ void __launch_bounds__(TPB_B, 6) emd_query_kernel(
    float* __restrict__ out,
    const float* __restrict__ eps_p, const int* __restrict__ iters_p,
    int write_assign) {
    int lane = threadIdx.x & 31;                      // lane in warp
    int sub  = lane & (GSIZE - 1);                    // lane in 8-group
    int grp  = threadIdx.x >> 3;                      // group in block
    int gid  = blockIdx.x * QPB + grp;                // sorted query slot
    int b    = gid >> 11;                             // batch (same for block)

    // Stage this batch's candidate cell-start table into smem.
    __shared__ int scs[CELLS + 1];
    {
        const int* __restrict__ cs = g_cs + b * (CELLS + 1);
        #pragma unroll
        for (int c = threadIdx.x; c < CELLS + 1; c += TPB_B) scs[c] = cs[c];
    }
    __syncthreads();

    // Cell-sorted query: spatially adjacent to neighbors in the warp/block.
    float4 qp = g_qpts[gid];
    float x = qp.x, y = qp.y, z = qp.z;
    int orig = __float_as_int(qp.w);                  // original row in batch
    float sq1 = __fadd_rn(__fadd_rn(__fmul_rn(x, x), __fmul_rn(y, y)),
                          __fmul_rn(z, z));
    int cx = cell_coord(x), cy = cell_coord(y), cz = cell_coord(z);

    const float4* __restrict__ pts = g_pts + b * NPTS;

    auto scan_range = [&](float qx, float qy, float qz, float qs,
                          int s, int e, u64& acc) {
        for (int k = s; k < e; k++) {
            float4 p = pts[k];
            float w = __fadd_rn(
                __fadd_rn(__fmul_rn(p.x, p.x), __fmul_rn(p.y, p.y)),
                __fmul_rn(p.z, p.z));
            float inner = __fmaf_rn(qz, p.z,
                          __fmaf_rn(qy, p.y, __fmul_rn(qx, p.x)));
            float d2 = __fmaf_rn(-2.0f, inner, __fadd_rn(qs, w));
            u64 key = ((u64)__float_as_uint(d2) << 32) |
                      (unsigned)__float_as_int(p.w);
            if (key < acc) acc = key;
        }
    };
    auto row_range = [&](int zc, int yc, int xlo, int xhi, int& s, int& e) {
        if ((unsigned)zc >= G || (unsigned)yc >= G) { s = 0; e = 0; return; }
        int row = (zc * G + yc) * G;
        s = scs[row + xlo];
        e = scs[row + xhi + 1];
    };

    u64 best = 0xFFFFFFFFFFFFFFFFull;

    // ---- fast path: r=1 cube, 9 rows over 8 lanes ----
    {
        int xlo = cx - 1 < 0 ? 0 : cx - 1;
        int xhi = cx + 1 > G - 1 ? G - 1 : cx + 1;
        int s0, e0, s1 = 0, e1 = 0;
        {
            int dz = sub / 3 - 1;                     // constant div -> mul
            int dy = sub - (sub / 3) * 3 - 1;
            row_range(cz + dz, cy + dy, xlo, xhi, s0, e0);
        }
        if (sub == 0)                                  // rowid 8 = (+1,+1)
            row_range(cz + 1, cy + 1, xlo, xhi, s1, e1);
        scan_range(x, y, z, sq1, s0, e0, best);
        if (sub == 0) scan_range(x, y, z, sq1, s1, e1, best);
        #pragma unroll
        for (int off = GSIZE / 2; off > 0; off >>= 1) {
            u64 o = __shfl_xor_sync(0xFFFFFFFFu, best, off);
            if (o < best) best = o;
        }
    }
    float bd2 = __uint_as_float((unsigned)(best >> 32));
    bool done = (bd2 < HCELL * HCELL - 1e-5f);

    // ---- warp-cooperative slow path ----
    unsigned pending = __ballot_sync(0xFFFFFFFFu, sub == 0 && !done);
    while (pending) {
        int src = __ffs(pending) - 1;
        pending &= pending - 1;
        float qx = __shfl_sync(0xFFFFFFFFu, x,   src);
        float qy = __shfl_sync(0xFFFFFFFFu, y,   src);
        float qz = __shfl_sync(0xFFFFFFFFu, z,   src);
        float qs = __shfl_sync(0xFFFFFFFFu, sq1, src);
        int  qcx = __shfl_sync(0xFFFFFFFFu, cx,  src);
        int  qcy = __shfl_sync(0xFFFFFFFFu, cy,  src);
        int  qcz = __shfl_sync(0xFFFFFFFFu, cz,  src);
        u64 wb   = __shfl_sync(0xFFFFFFFFu, best, src);

        {   // r=2: 25 rows over 32 lanes, ny=5 compile-time
            int xlo = qcx - 2 < 0 ? 0 : qcx - 2;
            int xhi = qcx + 2 > G - 1 ? G - 1 : qcx + 2;
            if (lane < 25) {
                int dz = lane / 5 - 2;
                int dy = lane - (lane / 5) * 5 - 2;
                int s, e;
                row_range(qcz + dz, qcy + dy, xlo, xhi, s, e);
                scan_range(qx, qy, qz, qs, s, e, wb);
            }
            #pragma unroll
            for (int off = 16; off > 0; off >>= 1) {
                u64 o = __shfl_xor_sync(0xFFFFFFFFu, wb, off);
                if (o < wb) wb = o;
            }
        }
        float wd2 = __uint_as_float((unsigned)(wb >> 32));
        if (!(wd2 < 4.0f * HCELL * HCELL - 1e-5f)) {
            for (int r = 3; r <= G; r++) {            // rare; r==G covers grid
                int ny = 2 * r + 1, nrow = ny * ny;
                int xlo = qcx - r < 0 ? 0 : qcx - r;
                int xhi = qcx + r > G - 1 ? G - 1 : qcx + r;
                for (int t = lane; t < nrow; t += 32) {
                    int qd = t / ny;
                    int s, e;
                    row_range(qcz - r + qd, qcy - r + (t - qd * ny),
                              xlo, xhi, s, e);
                    scan_range(qx, qy, qz, qs, s, e, wb);
                }
                #pragma unroll
                for (int off = 16; off > 0; off >>= 1) {
                    u64 o = __shfl_xor_sync(0xFFFFFFFFu, wb, off);
                    if (o < wb) wb = o;
                }
                wd2 = __uint_as_float((unsigned)(wb >> 32));
                float rh = (float)r * HCELL;
                if (wd2 < rh * rh - 1e-5f) break;
            }
        }
        if (lane == src) best = wb;
    }

    // ---- epilogue: one active lane per query; scatter to original row ----
    if (sub == 0) {
        float d2 = __uint_as_float((unsigned)(best >> 32));
        int   aj = (int)(best & 0xFFFFFFFFu);

        float cmin = sqrtf(fmaxf(d2, 0.0f));          // IEEE sqrt
        float eps  = eps_p   ? *eps_p   : 0.005f;
        int   iters = iters_p ? *iters_p : 50;

        float price = 0.0f;
        float m = 0.0f;
        if (iters == 50) {
            #pragma unroll
            for (int t = 0; t < 50; t++) {
                m = __fadd_rn(cmin, -price);
                price = __fadd_rn(price, __fmul_rn(eps, m));
            }
        } else {
            for (int t = 0; t < iters; t++) {
                m = __fadd_rn(cmin, -price);
                price = __fadd_rn(price, __fmul_rn(eps, m));
            }
        }

        int row = b * NPTS + orig;
        out[row] = sqrtf(m);
        if (write_assign) out[ROWS + row] = (float)aj;
    }
}

extern "C" void kernel_launch(void* const* d_in, const int* in_sizes, int n_in,
                              void* d_out, int out_size) {
    const float* x1 = (const float*)d_in[0];
    const float* x2 = (const float*)d_in[1];
    const float* eps_p   = (n_in > 2) ? (const float*)d_in[2] : nullptr;
    const int*   iters_p = (n_in > 3) ? (const int*)d_in[3]   : nullptr;

    emd_bin_kernel<<<2 * BATCH, TPB_A>>>(x2, x1);     // sorts both sets

    int write_assign = (out_size >= 2 * ROWS) ? 1 : 0;
    emd_query_kernel<<<ROWS / QPB, TPB_B>>>((float*)d_out,
                                            eps_p, iters_p, write_assign);
}

// round 16
// speedup vs baseline: 1.0860x; 1.0860x over previous
#include <cuda_runtime.h>
#include <cuda_bf16.h>

// emdModule: exact NN via uniform-grid spatial hashing + 50-step recurrence.
// Kernel B stages the ENTIRE per-batch candidate table (32KB pts + 16KB cell
// starts = 48KB) into shared memory: every candidate access in the hot loop is
// a 29-cyc LDS instead of a ~240-cyc L2 LDG. 8 lanes/query fast path (r=1
// cube); warp-cooperative slow path for r>=2. Queries are cell-sorted too
// (clusters slow queries into the same warps).
//
// EXACTNESS (outputs bit-identical to the passing brute-force kernels):
//  - d2 per examined candidate uses the identical rounded op sequence:
//      w     = (a*a + b*b) + c*c          (mul/add, no fma)
//      inner = fma(z,c, fma(y,b, x*a))
//      d2    = fma(-2, inner, sq1 + w)
//  - selection = min over packed key (bits(d2)<<32 | j): order- and
//    duplication-independent; ties -> smaller j == jnp.argmin first-index.
//  - completeness: after the Chebyshev<=r cube, any unexamined point is >= r
//    cells away on some axis => exact dist >= r*h => rounded d2 >= (r*h)^2-2e-6.
//    Stop only when best_d2 < (r*h)^2 - 1e-5; r == G covers the whole grid.
//  - query processing order irrelevant; results scattered to original rows.
//  - epilogue identical: cmin = sqrt(max(d2,0)); iters x {m = cmin - price;
//    price += eps*m}; outputs sqrt(m), assignment.

#define BATCH 16
#define NPTS 2048
#define ROWS (BATCH * NPTS)   // 32768
#define G 16                  // grid resolution per axis
#define CELLS (G * G * G)     // 4096
#define HCELL 0.0625f         // 1/G, exactly representable

__device__ float4 g_pts[BATCH * NPTS];          // x2 {a,b,c, j-bits} sorted
__device__ int    g_cs[BATCH * (CELLS + 1)];    // x2 cell starts + sentinel
__device__ float4 g_qpts[BATCH * NPTS];         // x1 {x,y,z, i-bits} sorted
__device__ int    g_qcs[BATCH * (CELLS + 1)];   // x1 cell starts (unused)

__device__ __forceinline__ int cell_coord(float v) {
    int c = (int)(v * (float)G);
    return c < 0 ? 0 : (c > G - 1 ? G - 1 : c);
}

// -------- Kernel A: counting sort into cells (runs for x2 AND x1) ----------
#define TPB_A 512
#define PPT_A (NPTS / TPB_A)      // 4 points per thread
#define CPT_A (CELLS / TPB_A)     // 8 cells per thread

__global__ void __launch_bounds__(TPB_A) emd_bin_kernel(
    const float* __restrict__ x2, const float* __restrict__ x1) {
    int which = blockIdx.x >> 4;                  // 0: candidates, 1: queries
    int b     = blockIdx.x & (BATCH - 1);
    const float* src = which ? x1 : x2;
    float4* opts = (which ? g_qpts : g_pts) + b * NPTS;
    int*    ocs  = (which ? g_qcs  : g_cs)  + b * (CELLS + 1);
    int t = threadIdx.x;
    __shared__ int cnt[CELLS];
    __shared__ int wsum[16];

    for (int c = t; c < CELLS; c += TPB_A) cnt[c] = 0;
    __syncthreads();

    int   cellof[PPT_A];
    float px[PPT_A], py[PPT_A], pz[PPT_A];
    #pragma unroll
    for (int s = 0; s < PPT_A; s++) {
        int k = t + s * TPB_A;
        const float* p = src + ((long)b * NPTS + k) * 3;
        float a = p[0], bb = p[1], cc = p[2];
        int c = (cell_coord(cc) * G + cell_coord(bb)) * G + cell_coord(a);
        px[s] = a; py[s] = bb; pz[s] = cc; cellof[s] = c;
        atomicAdd(&cnt[c], 1);
    }
    __syncthreads();

    int loc[CPT_A], tsum = 0;
    #pragma unroll
    for (int u = 0; u < CPT_A; u++) { loc[u] = cnt[t * CPT_A + u]; tsum += loc[u]; }
    int lane = t & 31, wid = t >> 5;
    int incl = tsum;
    #pragma unroll
    for (int off = 1; off < 32; off <<= 1) {
        int v = __shfl_up_sync(0xFFFFFFFFu, incl, off);
        if (lane >= off) incl += v;
    }
    if (lane == 31) wsum[wid] = incl;
    __syncthreads();
    if (t == 0) {
        int acc = 0;
        #pragma unroll
        for (int w = 0; w < 16; w++) { int v = wsum[w]; wsum[w] = acc; acc += v; }
    }
    __syncthreads();
    int run = wsum[wid] + (incl - tsum);
    __syncthreads();
    #pragma unroll
    for (int u = 0; u < CPT_A; u++) {
        int c = t * CPT_A + u;
        ocs[c] = run;
        cnt[c] = run;
        run += loc[u];
    }
    if (t == 0) ocs[CELLS] = NPTS;
    __syncthreads();

    #pragma unroll
    for (int s = 0; s < PPT_A; s++) {
        int k = t + s * TPB_A;
        int slot = atomicAdd(&cnt[cellof[s]], 1);
        opts[slot] = make_float4(px[s], py[s], pz[s], __int_as_float(k));
    }
}

// ---------------- Kernel B: smem-resident grid NN + epilogue ---------------
typedef unsigned long long u64;
#define TPB_B 256
#define GSIZE 8
#define QPB 64                        // queries per block (64 | 2048: no
                                      // block straddles a batch)
#define QROUNDS (QPB / (TPB_B / GSIZE))  // 2 queries per 8-lane group

__global__ void __launch_bounds__(TPB_B, 4) emd_query_kernel(
    float* __restrict__ out,
    const float* __restrict__ eps_p, const int* __restrict__ iters_p,
    int write_assign) {
    int lane = threadIdx.x & 31;
    int sub  = lane & (GSIZE - 1);
    int grp  = threadIdx.x >> 3;                      // 0..31
    int base = blockIdx.x * QPB;
    int b    = base >> 11;                            // batch (block-uniform)

    // Stage the ENTIRE per-batch candidate table into smem (48KB exactly;
    // scs has no sentinel -- index CELLS selects the constant NPTS).
    __shared__ float4 spts[NPTS];                     // 32 KB
    __shared__ int    scs[CELLS];                     // 16 KB
    {
        const float4* __restrict__ gp = g_pts + b * NPTS;
        const int*    __restrict__ gc = g_cs + b * (CELLS + 1);
        #pragma unroll
        for (int k = threadIdx.x; k < NPTS; k += TPB_B) spts[k] = gp[k];
        #pragma unroll
        for (int c = threadIdx.x; c < CELLS; c += TPB_B) scs[c] = gc[c];
    }
    __syncthreads();

    auto scan_range = [&](float qx, float qy, float qz, float qs,
                          int s, int e, u64& acc) {
        for (int k = s; k < e; k++) {
            float4 p = spts[k];                        // LDS, not LDG
            float w = __fadd_rn(
                __fadd_rn(__fmul_rn(p.x, p.x), __fmul_rn(p.y, p.y)),
                __fmul_rn(p.z, p.z));
            float inner = __fmaf_rn(qz, p.z,
                          __fmaf_rn(qy, p.y, __fmul_rn(qx, p.x)));
            float d2 = __fmaf_rn(-2.0f, inner, __fadd_rn(qs, w));
            u64 key = ((u64)__float_as_uint(d2) << 32) |
                      (unsigned)__float_as_int(p.w);
            if (key < acc) acc = key;
        }
    };
    auto row_range = [&](int zc, int yc, int xlo, int xhi, int& s, int& e) {
        if ((unsigned)zc >= G || (unsigned)yc >= G) { s = 0; e = 0; return; }
        int row = (zc * G + yc) * G;
        s = scs[row + xlo];
        int i2 = row + xhi + 1;
        e = (i2 < CELLS) ? scs[i2] : NPTS;             // sentinel via SEL
    };

    #pragma unroll 1
    for (int qi = 0; qi < QROUNDS; qi++) {
        int gid = base + qi * (TPB_B / GSIZE) + grp;   // sorted query slot

        float4 qp = g_qpts[gid];
        float x = qp.x, y = qp.y, z = qp.z;
        int orig = __float_as_int(qp.w);               // original row in batch
        float sq1 = __fadd_rn(__fadd_rn(__fmul_rn(x, x), __fmul_rn(y, y)),
                              __fmul_rn(z, z));
        int cx = cell_coord(x), cy = cell_coord(y), cz = cell_coord(z);

        u64 best = 0xFFFFFFFFFFFFFFFFull;

        // ---- fast path: r=1 cube, 9 rows over 8 lanes ----
        {
            int xlo = cx - 1 < 0 ? 0 : cx - 1;
            int xhi = cx + 1 > G - 1 ? G - 1 : cx + 1;
            int s0, e0, s1 = 0, e1 = 0;
            {
                int dz = sub / 3 - 1;                  // constant div -> mul
                int dy = sub - (sub / 3) * 3 - 1;
                row_range(cz + dz, cy + dy, xlo, xhi, s0, e0);
            }
            if (sub == 0)                              // rowid 8 = (+1,+1)
                row_range(cz + 1, cy + 1, xlo, xhi, s1, e1);
            scan_range(x, y, z, sq1, s0, e0, best);
            if (sub == 0) scan_range(x, y, z, sq1, s1, e1, best);
            #pragma unroll
            for (int off = GSIZE / 2; off > 0; off >>= 1) {
                u64 o = __shfl_xor_sync(0xFFFFFFFFu, best, off);
                if (o < best) best = o;
            }
        }
        float bd2 = __uint_as_float((unsigned)(best >> 32));
        bool done = (bd2 < HCELL * HCELL - 1e-5f);

        // ---- warp-cooperative slow path ----
        unsigned pending = __ballot_sync(0xFFFFFFFFu, sub == 0 && !done);
        while (pending) {
            int src = __ffs(pending) - 1;
            pending &= pending - 1;
            float qx = __shfl_sync(0xFFFFFFFFu, x,   src);
            float qy = __shfl_sync(0xFFFFFFFFu, y,   src);
            float qz = __shfl_sync(0xFFFFFFFFu, z,   src);
            float qs = __shfl_sync(0xFFFFFFFFu, sq1, src);
            int  qcx = __shfl_sync(0xFFFFFFFFu, cx,  src);
            int  qcy = __shfl_sync(0xFFFFFFFFu, cy,  src);
            int  qcz = __shfl_sync(0xFFFFFFFFu, cz,  src);
            u64 wb   = __shfl_sync(0xFFFFFFFFu, best, src);

            {   // r=2: 25 rows over 32 lanes, ny=5 compile-time
                int xlo = qcx - 2 < 0 ? 0 : qcx - 2;
                int xhi = qcx + 2 > G - 1 ? G - 1 : qcx + 2;
                if (lane < 25) {
                    int dz = lane / 5 - 2;
                    int dy = lane - (lane / 5) * 5 - 2;
                    int s, e;
                    row_range(qcz + dz, qcy + dy, xlo, xhi, s, e);
                    scan_range(qx, qy, qz, qs, s, e, wb);
                }
                #pragma unroll
                for (int off = 16; off > 0; off >>= 1) {
                    u64 o = __shfl_xor_sync(0xFFFFFFFFu, wb, off);
                    if (o < wb) wb = o;
                }
            }
            float wd2 = __uint_as_float((unsigned)(wb >> 32));
            if (!(wd2 < 4.0f * HCELL * HCELL - 1e-5f)) {
                for (int r = 3; r <= G; r++) {         // rare; r==G covers grid
                    int ny = 2 * r + 1, nrow = ny * ny;
                    int xlo = qcx - r < 0 ? 0 : qcx - r;
                    int xhi = qcx + r > G - 1 ? G - 1 : qcx + r;
                    for (int t = lane; t < nrow; t += 32) {
                        int qd = t / ny;
                        int s, e;
                        row_range(qcz - r + qd, qcy - r + (t - qd * ny),
                                  xlo, xhi, s, e);
                        scan_range(qx, qy, qz, qs, s, e, wb);
                    }
                    #pragma unroll
                    for (int off = 16; off > 0; off >>= 1) {
                        u64 o = __shfl_xor_sync(0xFFFFFFFFu, wb, off);
                        if (o < wb) wb = o;
                    }
                    wd2 = __uint_as_float((unsigned)(wb >> 32));
                    float rh = (float)r * HCELL;
                    if (wd2 < rh * rh - 1e-5f) break;
                }
            }
            if (lane == src) best = wb;
        }

        // ---- epilogue: one active lane per query; scatter to orig row ----
        if (sub == 0) {
            float d2 = __uint_as_float((unsigned)(best >> 32));
            int   aj = (int)(best & 0xFFFFFFFFu);

            float cmin = sqrtf(fmaxf(d2, 0.0f));       // IEEE sqrt
            float eps  = eps_p   ? *eps_p   : 0.005f;
            int   iters = iters_p ? *iters_p : 50;

            float price = 0.0f;
            float m = 0.0f;
            if (iters == 50) {
                #pragma unroll
                for (int t = 0; t < 50; t++) {
                    m = __fadd_rn(cmin, -price);
                    price = __fadd_rn(price, __fmul_rn(eps, m));
                }
            } else {
                for (int t = 0; t < iters; t++) {
                    m = __fadd_rn(cmin, -price);
                    price = __fadd_rn(price, __fmul_rn(eps, m));
                }
            }

            int row = b * NPTS + orig;
            out[row] = sqrtf(m);
            if (write_assign) out[ROWS + row] = (float)aj;
        }
    }
}

extern "C" void kernel_launch(void* const* d_in, const int* in_sizes, int n_in,
                              void* d_out, int out_size) {
    const float* x1 = (const float*)d_in[0];
    const float* x2 = (const float*)d_in[1];
    const float* eps_p   = (n_in > 2) ? (const float*)d_in[2] : nullptr;
    const int*   iters_p = (n_in > 3) ? (const int*)d_in[3]   : nullptr;

    emd_bin_kernel<<<2 * BATCH, TPB_A>>>(x2, x1);     // sorts both sets

    int write_assign = (out_size >= 2 * ROWS) ? 1 : 0;
    emd_query_kernel<<<ROWS / QPB, TPB_B>>>((float*)d_out,
                                            eps_p, iters_p, write_assign);
}